// round 3
// baseline (speedup 1.0000x reference)
#include <cuda_runtime.h>
#include <cstdint>

// Problem constants (K=256, N=65536 fixed by the dataset)
#define KDIM   256
#define NTIME  65536
#define TCOLS  65535          // N-1 columns of S / GEMM
#define NCHUNK 512
#define CHUNKL 128            // NTIME / NCHUNK
#define WARMUP 32

#define GEMM_GRID 296         // 2 M-halves x 148
#define TILE_N    64
#define NTILES    1024        // ceil(TCOLS / TILE_N)

#define AS_STRIDE 260         // 256 + 4 pad (1040B, 16B aligned)
#define SS_STRIDE 260

// Scratch (device globals: allocation-free per harness rules)
__device__ float g_S[(size_t)NTIME * KDIM];        // S[j][k], tf32-rounded; j<TCOLS valid
__device__ float g_Atf[KDIM * KDIM];               // Alpha, tf32-rounded, row-major
__device__ float g_Mu0[KDIM];
__device__ float g_rowpart[NCHUNK * KDIM];         // partial row sums [chunk][k]
__device__ float g_partLL[1024];                   // loglik partials (zero-init, unused slots stay 0)

// ---------------------------------------------------------------------------
// Kernel 1: chunked exponential scan + row-sum partials.
// Each block = one time chunk, each thread = one row k. Warm-up of 32 steps
// makes chunks independent (carry error ~e^-32).
// ---------------------------------------------------------------------------
__global__ __launch_bounds__(256) void scan_kernel(const float* __restrict__ obs,
                                                   const float* __restrict__ Beta) {
    int k = threadIdx.x;
    int c = blockIdx.x;
    float beta  = Beta[k];
    float decay = expf(-beta);

    const float* orow = obs + (size_t)k * NTIME;
    int j0 = c * CHUNKL;
    int js = j0 - WARMUP; if (js < 0) js = 0;

    float h = 0.f;
    #pragma unroll 4
    for (int j = js; j < j0; ++j) h = decay * (h + orow[j]);

    float s = 0.f;
    int nstore = TCOLS - j0;                  // #stores in this chunk (<=CHUNKL)
    if (nstore > CHUNKL) nstore = CHUNKL;
    float* srow = g_S + (size_t)j0 * KDIM + k;
    #pragma unroll 4
    for (int i = 0; i < CHUNKL; ++i) {
        float o = orow[j0 + i];
        s += o;
        h = decay * (h + o);
        if (i < nstore) {
            float sv = beta * h;
            uint32_t u;
            asm("cvt.rna.tf32.f32 %0, %1;" : "=r"(u) : "f"(sv));
            srow[(size_t)i * KDIM] = __uint_as_float(u);
        }
    }
    g_rowpart[c * KDIM + k] = s;
}

// ---------------------------------------------------------------------------
// Kernel 2: prep. Block 0: Mu0, column-0 outputs, column-0 loglik term.
// Blocks 1..64: Alpha -> tf32.
// ---------------------------------------------------------------------------
__global__ __launch_bounds__(256) void prep_kernel(const float* __restrict__ obs,
                                                   const float* __restrict__ Alpha,
                                                   float* __restrict__ out) {
    int tid = threadIdx.x;
    if (blockIdx.x == 0) {
        float s = 0.f;
        for (int c = 0; c < NCHUNK; ++c) s += g_rowpart[c * KDIM + tid];
        float mean = s * (1.0f / (float)NTIME);
        float mu   = mean / 10.0f + 0.01f;
        g_Mu0[tid] = mu;
        // column 0: lams0 = mu, lams1 = 0
        out[1 + (size_t)tid * NTIME] = mu;
        out[1 + (size_t)KDIM * NTIME + (size_t)tid * NTIME] = 0.f;
        float ll = obs[(size_t)tid * NTIME] * __logf(mu + 1e-5f) - mu;
        __shared__ float red[256];
        red[tid] = ll;
        __syncthreads();
        for (int off = 128; off > 0; off >>= 1) {
            if (tid < off) red[tid] += red[tid + off];
            __syncthreads();
        }
        if (tid == 0) g_partLL[1023] = red[0];
    } else {
        int base = (blockIdx.x - 1) * 1024 + tid * 4;
        float4 v = *(const float4*)&Alpha[base];
        uint32_t u0, u1, u2, u3;
        asm("cvt.rna.tf32.f32 %0, %1;" : "=r"(u0) : "f"(v.x));
        asm("cvt.rna.tf32.f32 %0, %1;" : "=r"(u1) : "f"(v.y));
        asm("cvt.rna.tf32.f32 %0, %1;" : "=r"(u2) : "f"(v.z));
        asm("cvt.rna.tf32.f32 %0, %1;" : "=r"(u3) : "f"(v.w));
        float4 w = make_float4(__uint_as_float(u0), __uint_as_float(u1),
                               __uint_as_float(u2), __uint_as_float(u3));
        *(float4*)&g_Atf[base] = w;
    }
}

// ---------------------------------------------------------------------------
// Kernel 3: tf32 MMA GEMM (Lam = Alpha @ S) fused with softplus + lams0/lams1
// stores + loglik accumulation. CTA: 256 thr, M=128 (half), N=64 per tile,
// K=256 full. Persistent over tiles so Alpha smem is loaded once per CTA.
// ---------------------------------------------------------------------------
__device__ __forceinline__ void mma_tf32(float* d, const float* a, const float* b) {
    asm volatile(
        "mma.sync.aligned.m16n8k8.row.col.f32.tf32.tf32.f32 "
        "{%0,%1,%2,%3}, {%4,%5,%6,%7}, {%8,%9}, {%0,%1,%2,%3};"
        : "+f"(d[0]), "+f"(d[1]), "+f"(d[2]), "+f"(d[3])
        : "r"(__float_as_uint(a[0])), "r"(__float_as_uint(a[1])),
          "r"(__float_as_uint(a[2])), "r"(__float_as_uint(a[3])),
          "r"(__float_as_uint(b[0])), "r"(__float_as_uint(b[1])));
}

#define SMEM_FLOATS (128 * AS_STRIDE + 64 * SS_STRIDE + 128 + 256)
#define SMEM_BYTES  (SMEM_FLOATS * 4)

__global__ __launch_bounds__(256, 1) void gemm_kernel(const float* __restrict__ obs,
                                                      float* __restrict__ out) {
    extern __shared__ float sm[];
    float* As   = sm;                                   // [128][AS_STRIDE]
    float* Ss   = sm + 128 * AS_STRIDE;                 // [64][SS_STRIDE]
    float* Mu0s = sm + 128 * AS_STRIDE + 64 * SS_STRIDE;// [128]
    float* red  = Mu0s + 128;                           // [256]

    int tid   = threadIdx.x;
    int mhalf = blockIdx.x & 1;
    int tile0 = blockIdx.x >> 1;                        // 0..147
    int tstep = gridDim.x >> 1;                         // 148

    // Load this half of Alpha (tf32) into smem once.
    for (int f = tid; f < 128 * 64; f += 256) {         // 64 float4 per row
        int r  = f >> 6;
        int c4 = (f & 63) << 2;
        float4 v = *(const float4*)&g_Atf[((mhalf * 128 + r) << 8) + c4];
        float* dst = &As[r * AS_STRIDE + c4];
        dst[0] = v.x; dst[1] = v.y; dst[2] = v.z; dst[3] = v.w;
    }
    if (tid < 128) Mu0s[tid] = g_Mu0[mhalf * 128 + tid];

    int warp = tid >> 5, lane = tid & 31;
    int wm = warp & 3, wn = warp >> 2;                  // 4 x 2 warp grid
    int g  = lane >> 2, t = lane & 3;

    const float* aBase = &As[(wm * 32 + g) * AS_STRIDE + t];
    const float* bBase = &Ss[(wn * 32 + g) * SS_STRIDE + t];

    float* lams0base = out + 1;
    float* lams1base = out + 1 + (size_t)KDIM * NTIME;

    float llacc = 0.f;

    for (int tile = tile0; tile < NTILES; tile += tstep) {
        int j0 = tile << 6;
        __syncthreads();   // previous tile's Ss reads done (also covers A load)

        // Stage S tile: 64 columns (n) x 256 (k). thread -> (n = tid/4, q = tid%4)
        {
            int n = tid >> 2, q = tid & 3;
            const float4* src = (const float4*)&g_S[(size_t)(j0 + n) * KDIM + q * 64];
            float* dst = &Ss[n * SS_STRIDE + q * 64];
            #pragma unroll
            for (int i = 0; i < 16; ++i) {
                float4 v = src[i];
                dst[i * 4 + 0] = v.x; dst[i * 4 + 1] = v.y;
                dst[i * 4 + 2] = v.z; dst[i * 4 + 3] = v.w;
            }
        }
        __syncthreads();

        float acc[2][4][4];
        #pragma unroll
        for (int mi = 0; mi < 2; ++mi)
            #pragma unroll
            for (int ni = 0; ni < 4; ++ni)
                #pragma unroll
                for (int q = 0; q < 4; ++q) acc[mi][ni][q] = 0.f;

        #pragma unroll 4
        for (int ks = 0; ks < 32; ++ks) {
            int kk = ks << 3;
            float a[2][4], b[4][2];
            #pragma unroll
            for (int mi = 0; mi < 2; ++mi) {
                const float* ap = aBase + mi * 16 * AS_STRIDE + kk;
                a[mi][0] = ap[0];
                a[mi][1] = ap[8 * AS_STRIDE];
                a[mi][2] = ap[4];
                a[mi][3] = ap[8 * AS_STRIDE + 4];
            }
            #pragma unroll
            for (int ni = 0; ni < 4; ++ni) {
                const float* bp = bBase + ni * 8 * SS_STRIDE + kk;
                b[ni][0] = bp[0];
                b[ni][1] = bp[4];
            }
            #pragma unroll
            for (int mi = 0; mi < 2; ++mi)
                #pragma unroll
                for (int ni = 0; ni < 4; ++ni)
                    mma_tf32(acc[mi][ni], a[mi], b[ni]);
        }

        // Fused epilogue: softplus -> lams1, Mu0 -> lams0, loglik terms.
        #pragma unroll
        for (int mi = 0; mi < 2; ++mi) {
            #pragma unroll
            for (int rr = 0; rr < 2; ++rr) {
                int row = wm * 32 + mi * 16 + g + rr * 8;
                float mu = Mu0s[row];
                size_t grow = (size_t)(mhalf * 128 + row) * NTIME;
                #pragma unroll
                for (int ni = 0; ni < 4; ++ni) {
                    int jb = j0 + wn * 32 + ni * 8 + 2 * t;
                    #pragma unroll
                    for (int cc = 0; cc < 2; ++cc) {
                        int j = jb + cc;
                        if (j < TCOLS) {
                            float x = acc[mi][ni][rr * 2 + cc];   // x >= 0 (Alpha,S >= 0)
                            float lam1 = x + __logf(1.0f + __expf(-x));
                            size_t o = grow + (size_t)(j + 1);
                            lams0base[o] = mu;
                            lams1base[o] = lam1;
                            llacc += obs[o] * __logf(mu + lam1 + 1e-5f) - mu - lam1;
                        }
                    }
                }
            }
        }
    }

    // Deterministic CTA reduction of loglik partial.
    __syncthreads();
    red[tid] = llacc;
    __syncthreads();
    for (int off = 128; off > 0; off >>= 1) {
        if (tid < off) red[tid] += red[tid + off];
        __syncthreads();
    }
    if (tid == 0) g_partLL[blockIdx.x] = red[0];
}

// ---------------------------------------------------------------------------
// Kernel 4: final deterministic loglik sum (double accumulation).
// ---------------------------------------------------------------------------
__global__ __launch_bounds__(256) void final_kernel(float* __restrict__ out) {
    __shared__ double red[256];
    int tid = threadIdx.x;
    double s = 0.0;
    for (int i = tid; i < 1024; i += 256) s += (double)g_partLL[i];
    red[tid] = s;
    __syncthreads();
    for (int off = 128; off > 0; off >>= 1) {
        if (tid < off) red[tid] += red[tid + off];
        __syncthreads();
    }
    if (tid == 0) out[0] = (float)red[0];
}

// ---------------------------------------------------------------------------
extern "C" void kernel_launch(void* const* d_in, const int* in_sizes, int n_in,
                              void* d_out, int out_size) {
    const float* obs   = (const float*)d_in[0];   // [K, N]
    const float* Beta  = (const float*)d_in[1];   // [K]
    const float* Alpha = (const float*)d_in[2];   // [K, K]
    float* out = (float*)d_out;                   // [1 + K*N + K*N]

    scan_kernel<<<NCHUNK, 256>>>(obs, Beta);
    prep_kernel<<<65, 256>>>(obs, Alpha, out);

    cudaFuncSetAttribute(gemm_kernel, cudaFuncAttributeMaxDynamicSharedMemorySize, SMEM_BYTES);
    gemm_kernel<<<GEMM_GRID, 256, SMEM_BYTES>>>(obs, out);

    final_kernel<<<1, 256>>>(out);
}

// round 4
// speedup vs baseline: 1.6598x; 1.6598x over previous
#include <cuda_runtime.h>
#include <cstdint>

// Problem constants (K=256, N=65536 fixed)
#define KDIM    256
#define NTIME   65536
#define NCHUNK  512
#define CHUNKL  128
#define WARMUP  32

#define NTILES  1024          // 1024 tiles x 64 output columns t = 0..65535
#define TSTEP   148
#define GEMM_GRID 296         // 2 M-halves x 148

#define RSTRIDE 272           // floats per row in permuted smem layout (4 chunks x 68)
#define CSTRIDE 68            // floats per k-chunk

// Scratch (device globals; zero-initialized at module load)
__device__ float g_S[(size_t)NTIME * KDIM];   // g_S[t][k] = S for output column t (t=0 stays 0)
__device__ float g_Mu0[KDIM];
__device__ float g_rowpart[NCHUNK * KDIM];
__device__ float g_partLL[1024];              // slots >= GEMM_GRID stay 0

// ---------------------------------------------------------------------------
// Kernel 1: chunked exponential scan (warm-up makes chunks independent,
// decay <= e^-1 so carry error <= e^-32). float4 row streaming; stores
// tf32-rounded S at t = j+1, coalesced across k.
// ---------------------------------------------------------------------------
__global__ __launch_bounds__(256) void scan_kernel(const float* __restrict__ obs,
                                                   const float* __restrict__ Beta) {
    int k = threadIdx.x;
    int c = blockIdx.x;
    float beta  = Beta[k];
    float decay = expf(-beta);

    const float* orow = obs + ((size_t)k << 16);
    int j0 = c << 7;

    float h = 0.f;
    if (c > 0) {
        const float4* wp = (const float4*)(orow + j0 - WARMUP);
        #pragma unroll
        for (int i = 0; i < WARMUP / 4; ++i) {
            float4 v = wp[i];
            h = decay * (h + v.x); h = decay * (h + v.y);
            h = decay * (h + v.z); h = decay * (h + v.w);
        }
    }

    float s = 0.f;
    const float4* mp = (const float4*)(orow + j0);
    float* srow = g_S + (((size_t)(j0 + 1)) << 8) + k;
    int nstore = 65535 - j0; if (nstore > CHUNKL) nstore = CHUNKL;

    #pragma unroll 4
    for (int q = 0; q < CHUNKL / 4; ++q) {
        float4 v = mp[q];
        float vv[4] = {v.x, v.y, v.z, v.w};
        #pragma unroll
        for (int e = 0; e < 4; ++e) {
            float o = vv[e];
            s += o;
            h = decay * (h + o);
            int i = (q << 2) + e;
            if (i < nstore) {
                float sv = beta * h;
                uint32_t u;
                asm("cvt.rna.tf32.f32 %0, %1;" : "=r"(u) : "f"(sv));
                srow[(size_t)i << 8] = __uint_as_float(u);
            }
        }
    }
    g_rowpart[(c << 8) + k] = s;
}

// ---------------------------------------------------------------------------
// Kernel 2: Mu0 from chunk partial sums.
// ---------------------------------------------------------------------------
__global__ __launch_bounds__(256) void prep_kernel() {
    int k = threadIdx.x;
    float s = 0.f;
    for (int c = 0; c < NCHUNK; ++c) s += g_rowpart[(c << 8) + k];
    float mean = s * (1.0f / (float)NTIME);
    g_Mu0[k] = mean / 10.0f + 0.01f;
}

// ---------------------------------------------------------------------------
// Kernel 3: fused tf32 MMA GEMM + softplus + outputs + loglik.
// CTA: 512 thr (16 warps, 4x4 warp grid), M=128 (half of K rows), N=64/tile,
// K=256 full. Smem holds Alpha half (permuted, loaded once) + S tile (perm)
// reused as epilogue staging buffer for coalesced streaming.
// ---------------------------------------------------------------------------
__device__ __forceinline__ void mma_tf32(float* d, float a0, float a1, float a2,
                                         float a3, float b0, float b1) {
    asm volatile(
        "mma.sync.aligned.m16n8k8.row.col.f32.tf32.tf32.f32 "
        "{%0,%1,%2,%3}, {%4,%5,%6,%7}, {%8,%9}, {%0,%1,%2,%3};"
        : "+f"(d[0]), "+f"(d[1]), "+f"(d[2]), "+f"(d[3])
        : "r"(__float_as_uint(a0)), "r"(__float_as_uint(a1)),
          "r"(__float_as_uint(a2)), "r"(__float_as_uint(a3)),
          "r"(__float_as_uint(b0)), "r"(__float_as_uint(b1)));
}

#define SMEM_FLOATS (128 * RSTRIDE + 64 * RSTRIDE + 128 + 512)
#define SMEM_BYTES  (SMEM_FLOATS * 4)

__global__ __launch_bounds__(512, 1) void gemm_kernel(const float* __restrict__ obs,
                                                      const float* __restrict__ Alpha,
                                                      float* __restrict__ out) {
    extern __shared__ float sm[];
    float* As   = sm;                          // [128][RSTRIDE] permuted
    float* Ss   = sm + 128 * RSTRIDE;          // [64][RSTRIDE] permuted; reused as epi[128][CSTRIDE]
    float* Mu0s = sm + 128 * RSTRIDE + 64 * RSTRIDE;
    float* red  = Mu0s + 128;

    int tid   = threadIdx.x;
    int mhalf = blockIdx.x & 1;
    int tile0 = blockIdx.x >> 1;

    // ---- Stage this M-half of Alpha into smem (tf32 + k-permutation), once.
    {
        int r  = tid >> 2;                     // 0..127
        int qb = (tid & 3) << 4;
        const float4* src = (const float4*)(Alpha + (((size_t)((mhalf << 7) + r)) << 8));
        float* dst = As + r * RSTRIDE;
        #pragma unroll
        for (int i = 0; i < 16; ++i) {
            int q = qb + i;                    // float4 covers k = 4q..4q+3
            float4 v = src[q];
            uint32_t u0, u1, u2, u3;
            asm("cvt.rna.tf32.f32 %0, %1;" : "=r"(u0) : "f"(v.x));
            asm("cvt.rna.tf32.f32 %0, %1;" : "=r"(u1) : "f"(v.y));
            asm("cvt.rna.tf32.f32 %0, %1;" : "=r"(u2) : "f"(v.z));
            asm("cvt.rna.tf32.f32 %0, %1;" : "=r"(u3) : "f"(v.w));
            dst[q]               = __uint_as_float(u0);   // chunk c = k&3, u = k>>2
            dst[q + CSTRIDE]     = __uint_as_float(u1);
            dst[q + 2 * CSTRIDE] = __uint_as_float(u2);
            dst[q + 3 * CSTRIDE] = __uint_as_float(u3);
        }
    }
    if (tid < 128) Mu0s[tid] = g_Mu0[(mhalf << 7) + tid];

    int warp = tid >> 5, lane = tid & 31;
    int wm = warp & 3, wn = warp >> 2;         // 4 x 4 warp grid (M=32, N=16 per warp)
    int g  = lane >> 2, t = lane & 3;
    const float* aBase = As + ((wm << 5) + g) * RSTRIDE + t * CSTRIDE;
    const float* bBase = Ss + ((wn << 4) + g) * RSTRIDE + t * CSTRIDE;

    // ---- S tile register prefetch (64 cols x 256 k = 8 float4 / thread)
    int scol = tid >> 3, sq = tid & 7;
    float4 v[8];
    {
        const float4* src = (const float4*)(g_S + (((size_t)(tile0 << 6) + scol) << 8));
        #pragma unroll
        for (int i = 0; i < 8; ++i) v[i] = src[sq + (i << 3)];
    }

    int erow = tid >> 2;                       // epilogue: row 0..127
    int seg  = (tid & 3) << 4;                 // 16-col contiguous span

    float llacc = 0.f;

    for (int tile = tile0; tile < NTILES; tile += TSTEP) {
        __syncthreads();                       // epi reads of Ss done / As ready
        // STS prefetched S tile (permuted)
        {
            float* dst = Ss + scol * RSTRIDE;
            #pragma unroll
            for (int i = 0; i < 8; ++i) {
                int q = sq + (i << 3);
                dst[q]               = v[i].x;
                dst[q + CSTRIDE]     = v[i].y;
                dst[q + 2 * CSTRIDE] = v[i].z;
                dst[q + 3 * CSTRIDE] = v[i].w;
            }
        }
        __syncthreads();
        int ntile = tile + TSTEP;
        if (ntile < NTILES) {                  // overlap next LDG with MMA
            const float4* src = (const float4*)(g_S + (((size_t)(ntile << 6) + scol) << 8));
            #pragma unroll
            for (int i = 0; i < 8; ++i) v[i] = src[sq + (i << 3)];
        }

        float acc[2][2][4];
        #pragma unroll
        for (int mi = 0; mi < 2; ++mi)
            #pragma unroll
            for (int ni = 0; ni < 2; ++ni)
                #pragma unroll
                for (int q = 0; q < 4; ++q) acc[mi][ni][q] = 0.f;

        #pragma unroll
        for (int p = 0; p < 16; ++p) {         // each p = 2 k-steps (k16)
            float4 A0[2], A1[2], B0[2];
            #pragma unroll
            for (int mi = 0; mi < 2; ++mi) {
                A0[mi] = *(const float4*)(aBase + (mi << 4) * RSTRIDE + (p << 2));
                A1[mi] = *(const float4*)(aBase + ((mi << 4) + 8) * RSTRIDE + (p << 2));
            }
            #pragma unroll
            for (int ni = 0; ni < 2; ++ni)
                B0[ni] = *(const float4*)(bBase + (ni << 3) * RSTRIDE + (p << 2));
            #pragma unroll
            for (int mi = 0; mi < 2; ++mi)
                #pragma unroll
                for (int ni = 0; ni < 2; ++ni) {
                    mma_tf32(acc[mi][ni], A0[mi].x, A1[mi].x, A0[mi].y, A1[mi].y,
                             B0[ni].x, B0[ni].y);
                    mma_tf32(acc[mi][ni], A0[mi].z, A1[mi].z, A0[mi].w, A1[mi].w,
                             B0[ni].z, B0[ni].w);
                }
        }
        __syncthreads();                       // all MMA reads of Ss done

        // Stage accumulators into epi buffer (reuse Ss): epi[row][CSTRIDE]
        #pragma unroll
        for (int mi = 0; mi < 2; ++mi)
            #pragma unroll
            for (int rr = 0; rr < 2; ++rr) {
                int r = (wm << 5) + (mi << 4) + (rr << 3) + g;
                #pragma unroll
                for (int ni = 0; ni < 2; ++ni) {
                    int col = (wn << 4) + (ni << 3) + (t << 1);
                    float2 w = rr == 0 ? make_float2(acc[mi][ni][0], acc[mi][ni][1])
                                       : make_float2(acc[mi][ni][2], acc[mi][ni][3]);
                    *(float2*)(Ss + r * CSTRIDE + col) = w;
                }
            }
        __syncthreads();

        // Coalesced streaming epilogue: 16 contiguous columns per thread.
        {
            float mu = Mu0s[erow];
            size_t grow = ((size_t)((mhalf << 7) + erow)) << 16;
            int t0 = (tile << 6) + seg;
            const float* esrc = Ss + erow * CSTRIDE + seg;

            float lam[16];
            #pragma unroll
            for (int i = 0; i < 4; ++i) {
                float4 xv = *(const float4*)(esrc + (i << 2));
                float xs[4] = {xv.x, xv.y, xv.z, xv.w};
                #pragma unroll
                for (int e = 0; e < 4; ++e) {
                    float x = xs[e];                     // x >= 0
                    lam[(i << 2) + e] = x + __logf(1.0f + __expf(-x));
                }
            }
            if (tile == 0 && seg == 0) lam[0] = 0.f;     // column t=0: lams1 = 0

            const float4* op = (const float4*)(obs + grow + t0);
            #pragma unroll
            for (int i = 0; i < 4; ++i) {
                float4 ov = op[i];
                llacc += ov.x * __logf(mu + lam[(i << 2) + 0] + 1e-5f) - lam[(i << 2) + 0];
                llacc += ov.y * __logf(mu + lam[(i << 2) + 1] + 1e-5f) - lam[(i << 2) + 1];
                llacc += ov.z * __logf(mu + lam[(i << 2) + 2] + 1e-5f) - lam[(i << 2) + 2];
                llacc += ov.w * __logf(mu + lam[(i << 2) + 3] + 1e-5f) - lam[(i << 2) + 3];
            }
            llacc -= 16.f * mu;

            float* p0 = out + 1 + grow + t0;                           // lams0
            float* p1 = out + 1 + (((size_t)KDIM) << 16) + grow + t0;  // lams1
            // p0/p1 are (16B-4) aligned: 3 scalars, 3x float4, 1 scalar.
            p1[0] = lam[0]; p1[1] = lam[1]; p1[2] = lam[2];
            *(float4*)(p1 + 3)  = make_float4(lam[3],  lam[4],  lam[5],  lam[6]);
            *(float4*)(p1 + 7)  = make_float4(lam[7],  lam[8],  lam[9],  lam[10]);
            *(float4*)(p1 + 11) = make_float4(lam[11], lam[12], lam[13], lam[14]);
            p1[15] = lam[15];
            float4 muv = make_float4(mu, mu, mu, mu);
            p0[0] = mu; p0[1] = mu; p0[2] = mu;
            *(float4*)(p0 + 3) = muv; *(float4*)(p0 + 7) = muv; *(float4*)(p0 + 11) = muv;
            p0[15] = mu;
        }
    }

    // Deterministic CTA reduction.
    __syncthreads();
    red[tid] = llacc;
    __syncthreads();
    for (int off = 256; off > 0; off >>= 1) {
        if (tid < off) red[tid] += red[tid + off];
        __syncthreads();
    }
    if (tid == 0) g_partLL[blockIdx.x] = red[0];
}

// ---------------------------------------------------------------------------
// Kernel 4: final deterministic loglik sum (double accumulation).
// ---------------------------------------------------------------------------
__global__ __launch_bounds__(256) void final_kernel(float* __restrict__ out) {
    __shared__ double red[256];
    int tid = threadIdx.x;
    double s = 0.0;
    for (int i = tid; i < 1024; i += 256) s += (double)g_partLL[i];
    red[tid] = s;
    __syncthreads();
    for (int off = 128; off > 0; off >>= 1) {
        if (tid < off) red[tid] += red[tid + off];
        __syncthreads();
    }
    if (tid == 0) out[0] = (float)red[0];
}

// ---------------------------------------------------------------------------
extern "C" void kernel_launch(void* const* d_in, const int* in_sizes, int n_in,
                              void* d_out, int out_size) {
    const float* obs   = (const float*)d_in[0];   // [K, N]
    const float* Beta  = (const float*)d_in[1];   // [K]
    const float* Alpha = (const float*)d_in[2];   // [K, K]
    float* out = (float*)d_out;                   // [1 + K*N + K*N]

    scan_kernel<<<NCHUNK, 256>>>(obs, Beta);
    prep_kernel<<<1, 256>>>();

    cudaFuncSetAttribute(gemm_kernel, cudaFuncAttributeMaxDynamicSharedMemorySize, SMEM_BYTES);
    gemm_kernel<<<GEMM_GRID, 512, SMEM_BYTES>>>(obs, Alpha, out);

    final_kernel<<<1, 256>>>(out);
}

// round 10
// speedup vs baseline: 2.3047x; 1.3885x over previous
#include <cuda_runtime.h>
#include <cuda_bf16.h>
#include <cstdint>

// Problem constants (K=256, N=65536 fixed)
#define KDIM    256
#define NTIME   65536
#define NCHUNK  512
#define CHUNKL  128
#define WARMUP  32

#define NTILES  1024          // 1024 tiles x 64 output columns t = 0..65535
#define GRID    148           // single wave, persistent tiles

#define CS      36            // u32 (bf16-pair) per k-chunk in permuted smem
#define RS      144           // u32 per row (4 chunks x 36); 576B, 16B-multiple
#define EPI_STRIDE 68         // floats per row of epilogue staging (mult of 4!)

// Scratch (device globals; zero-initialized at module load)
__device__ __align__(16) __nv_bfloat16 g_S[(size_t)NTIME * KDIM]; // S[t][k]; row t=0 stays 0
__device__ float g_Mu0[KDIM];
__device__ float g_rowpart[NCHUNK * KDIM];
__device__ float g_partLL[1024];                     // slots >= GRID stay 0

__device__ __forceinline__ uint32_t pack_bf16(float lo, float hi) {
    __nv_bfloat162 p = __floats2bfloat162_rn(lo, hi);
    return *reinterpret_cast<uint32_t*>(&p);
}

// ---------------------------------------------------------------------------
// Kernel 1: chunked exponential scan (WARMUP makes chunks independent; decay
// <= e^-1 so carry error <= e^-32). Stores bf16 S at t = j+1, coalesced in k.
// ---------------------------------------------------------------------------
__global__ __launch_bounds__(256) void scan_kernel(const float* __restrict__ obs,
                                                   const float* __restrict__ Beta) {
    int k = threadIdx.x;
    int c = blockIdx.x;
    float beta  = Beta[k];
    float decay = expf(-beta);

    const float* orow = obs + ((size_t)k << 16);
    int j0 = c << 7;

    float h = 0.f;
    if (c > 0) {
        const float4* wp = (const float4*)(orow + j0 - WARMUP);
        #pragma unroll
        for (int i = 0; i < WARMUP / 4; ++i) {
            float4 v = wp[i];
            h = decay * (h + v.x); h = decay * (h + v.y);
            h = decay * (h + v.z); h = decay * (h + v.w);
        }
    }

    float s = 0.f;
    const float4* mp = (const float4*)(orow + j0);
    __nv_bfloat16* srow = g_S + (((size_t)(j0 + 1)) << 8) + k;
    int nstore = 65535 - j0; if (nstore > CHUNKL) nstore = CHUNKL;

    #pragma unroll 4
    for (int q = 0; q < CHUNKL / 4; ++q) {
        float4 v = mp[q];
        float vv[4] = {v.x, v.y, v.z, v.w};
        #pragma unroll
        for (int e = 0; e < 4; ++e) {
            float o = vv[e];
            s += o;
            h = decay * (h + o);
            int i = (q << 2) + e;
            if (i < nstore) srow[(size_t)i << 8] = __float2bfloat16_rn(beta * h);
        }
    }
    g_rowpart[(c << 8) + k] = s;
}

// ---------------------------------------------------------------------------
// Kernel 2: Mu0 from chunk partial sums.
// ---------------------------------------------------------------------------
__global__ __launch_bounds__(256) void prep_kernel() {
    int k = threadIdx.x;
    float s = 0.f;
    for (int c = 0; c < NCHUNK; ++c) s += g_rowpart[(c << 8) + k];
    float mean = s * (1.0f / (float)NTIME);
    g_Mu0[k] = mean / 10.0f + 0.01f;
}

// ---------------------------------------------------------------------------
// Kernel 3: fused bf16 MMA GEMM (Lam = Alpha @ S^T per column) + softplus +
// lams0/lams1 stores + loglik. One CTA per SM, full M=256, N=64 per tile,
// K=256. A held in smem bf16 (pair-permuted) for the whole kernel.
// ---------------------------------------------------------------------------
__device__ __forceinline__ void mma_bf16(float* d, uint32_t a0, uint32_t a1,
                                         uint32_t a2, uint32_t a3,
                                         uint32_t b0, uint32_t b1) {
    asm volatile(
        "mma.sync.aligned.m16n8k16.row.col.f32.bf16.bf16.f32 "
        "{%0,%1,%2,%3}, {%4,%5,%6,%7}, {%8,%9}, {%0,%1,%2,%3};"
        : "+f"(d[0]), "+f"(d[1]), "+f"(d[2]), "+f"(d[3])
        : "r"(a0), "r"(a1), "r"(a2), "r"(a3), "r"(b0), "r"(b1));
}

#define SMEM_U32   (256 * RS + 64 * RS)
#define SMEM_BYTES ((SMEM_U32 + 256 + 512) * 4)

__global__ __launch_bounds__(512, 1) void gemm_kernel(const float* __restrict__ obs,
                                                      const float* __restrict__ Alpha,
                                                      float* __restrict__ out) {
    extern __shared__ uint32_t smu[];
    uint32_t* As  = smu;                        // [256][RS] bf16-pairs, permuted
    uint32_t* Ss  = smu + 256 * RS;             // [64][RS]; overlaid as epi[128][EPI_STRIDE] floats
    float*    epi = (float*)Ss;
    float*   Mu0s = (float*)(smu + SMEM_U32);
    float*    red = Mu0s + 256;

    int tid   = threadIdx.x;
    int tile0 = blockIdx.x;

    // ---- Stage full Alpha into smem (bf16 pairs, permuted), once.
    {
        int r = tid >> 1, half = tid & 1;
        const float4* src = (const float4*)(Alpha + ((size_t)r << 8)) + half * 32;
        uint32_t* dst = As + r * RS;
        #pragma unroll
        for (int i = 0; i < 32; ++i) {
            int f = half * 32 + i;              // float4 index: k = 4f..4f+3, pairs 2f, 2f+1
            float4 v = src[i];
            int j0 = 2 * f, j1 = 2 * f + 1;
            dst[(j0 & 3) * CS + (j0 >> 2)] = pack_bf16(v.x, v.y);
            dst[(j1 & 3) * CS + (j1 >> 2)] = pack_bf16(v.z, v.w);
        }
    }
    if (tid < 256) Mu0s[tid] = g_Mu0[tid];

    int warp = tid >> 5, lane = tid & 31;
    int wm = warp & 3, wn = warp >> 2;          // 4x4 warp grid: M=64, N=16 per warp
    int g  = lane >> 2, t = lane & 3;
    const uint32_t* aB = As + (wm * 64 + g) * RS + t * CS;
    const uint32_t* bB = Ss + (wn * 16 + g) * RS + t * CS;

    // ---- S tile register prefetch: 64 rows x 128 u32; 8 threads/row, 4 uint4 each.
    int scol = tid >> 3, sq = tid & 7;
    uint4 v[4];
    {
        const uint4* src = (const uint4*)g_S + ((size_t)(tile0 * 64 + scol) * 32) + sq * 4;
        #pragma unroll
        for (int i = 0; i < 4; ++i) v[i] = src[i];
    }

    int erow = tid >> 2;                        // epilogue row 0..127 within half
    int seg  = (tid & 3) << 4;                  // 16-col contiguous span

    float llacc = 0.f;

    for (int tile = tile0; tile < NTILES; tile += GRID) {
        __syncthreads();                        // prev epi reads done; As staged (first iter)
        // STS prefetched S tile (permuted): u32 j -> pos (j&3)*CS + (j>>2)
        {
            uint32_t* dst = Ss + scol * RS;
            #pragma unroll
            for (int i = 0; i < 4; ++i) {
                int u = 4 * sq + i;             // j = 4u .. covers chunks 0..3 at index u
                dst[u]          = v[i].x;
                dst[CS + u]     = v[i].y;
                dst[2 * CS + u] = v[i].z;
                dst[3 * CS + u] = v[i].w;
            }
        }
        __syncthreads();
        int ntile = tile + GRID;
        if (ntile < NTILES) {                   // overlap next LDG with MMA
            const uint4* src = (const uint4*)g_S + ((size_t)(ntile * 64 + scol) * 32) + sq * 4;
            #pragma unroll
            for (int i = 0; i < 4; ++i) v[i] = src[i];
        }

        float acc[4][2][4];
        #pragma unroll
        for (int mt = 0; mt < 4; ++mt)
            #pragma unroll
            for (int nt = 0; nt < 2; ++nt)
                #pragma unroll
                for (int q = 0; q < 4; ++q) acc[mt][nt][q] = 0.f;

        #pragma unroll
        for (int q = 0; q < 8; ++q) {           // each q = 2 k16 blocks
            uint4 Ag[4], Ah[4], Bn[2];
            #pragma unroll
            for (int mt = 0; mt < 4; ++mt) {
                Ag[mt] = *(const uint4*)(aB + (mt * 16) * RS + 4 * q);
                Ah[mt] = *(const uint4*)(aB + (mt * 16 + 8) * RS + 4 * q);
            }
            #pragma unroll
            for (int nt = 0; nt < 2; ++nt)
                Bn[nt] = *(const uint4*)(bB + (nt * 8) * RS + 4 * q);
            #pragma unroll
            for (int mt = 0; mt < 4; ++mt)
                #pragma unroll
                for (int nt = 0; nt < 2; ++nt) {
                    mma_bf16(acc[mt][nt], Ag[mt].x, Ah[mt].x, Ag[mt].y, Ah[mt].y,
                             Bn[nt].x, Bn[nt].y);
                    mma_bf16(acc[mt][nt], Ag[mt].z, Ah[mt].z, Ag[mt].w, Ah[mt].w,
                             Bn[nt].z, Bn[nt].w);
                }
        }

        // ---- Two half-passes: stage acc rows into epi buffer, stream epilogue.
        #pragma unroll
        for (int hp = 0; hp < 2; ++hp) {
            __syncthreads();                    // MMA Ss reads / prev epi reads done
            if ((wm >> 1) == hp) {
                int lr = (wm & 1) * 64 + g;     // local row (plus mt*16, +8)
                #pragma unroll
                for (int mt = 0; mt < 4; ++mt)
                    #pragma unroll
                    for (int nt = 0; nt < 2; ++nt) {
                        int col = wn * 16 + nt * 8 + 2 * t;
                        float* e0 = epi + (lr + mt * 16) * EPI_STRIDE + col;
                        *(float2*)e0 = make_float2(acc[mt][nt][0], acc[mt][nt][1]);
                        *(float2*)(e0 + 8 * EPI_STRIDE) =
                            make_float2(acc[mt][nt][2], acc[mt][nt][3]);
                    }
            }
            __syncthreads();

            // Coalesced streaming epilogue: 16 contiguous columns per thread.
            int row = hp * 128 + erow;
            float mu = Mu0s[row];
            size_t grow = ((size_t)row) << 16;
            int t0 = (tile << 6) + seg;
            const float* esrc = epi + erow * EPI_STRIDE + seg;

            float lam[16];
            #pragma unroll
            for (int i = 0; i < 4; ++i) {
                float4 xv = *(const float4*)(esrc + (i << 2));
                float xs[4] = {xv.x, xv.y, xv.z, xv.w};
                #pragma unroll
                for (int e = 0; e < 4; ++e) {
                    float x = xs[e];                      // x >= 0
                    lam[(i << 2) + e] = x + __logf(1.0f + __expf(-x));
                }
            }
            if (tile == 0 && seg == 0) lam[0] = 0.f;      // column t=0: lams1 = 0

            const float4* op = (const float4*)(obs + grow + t0);
            #pragma unroll
            for (int i = 0; i < 4; ++i) {
                float4 ov = op[i];
                llacc += ov.x * __logf(mu + lam[(i << 2) + 0] + 1e-5f) - lam[(i << 2) + 0];
                llacc += ov.y * __logf(mu + lam[(i << 2) + 1] + 1e-5f) - lam[(i << 2) + 1];
                llacc += ov.z * __logf(mu + lam[(i << 2) + 2] + 1e-5f) - lam[(i << 2) + 2];
                llacc += ov.w * __logf(mu + lam[(i << 2) + 3] + 1e-5f) - lam[(i << 2) + 3];
            }
            llacc -= 16.f * mu;

            float* p0 = out + 1 + grow + t0;                           // lams0
            float* p1 = out + 1 + (((size_t)KDIM) << 16) + grow + t0;  // lams1
            // p0/p1 are (16B-4) aligned: 3 scalars, 3x float4, 1 scalar.
            p1[0] = lam[0]; p1[1] = lam[1]; p1[2] = lam[2];
            *(float4*)(p1 + 3)  = make_float4(lam[3],  lam[4],  lam[5],  lam[6]);
            *(float4*)(p1 + 7)  = make_float4(lam[7],  lam[8],  lam[9],  lam[10]);
            *(float4*)(p1 + 11) = make_float4(lam[11], lam[12], lam[13], lam[14]);
            p1[15] = lam[15];
            float4 muv = make_float4(mu, mu, mu, mu);
            p0[0] = mu; p0[1] = mu; p0[2] = mu;
            *(float4*)(p0 + 3) = muv; *(float4*)(p0 + 7) = muv; *(float4*)(p0 + 11) = muv;
            p0[15] = mu;
        }
    }

    // Deterministic CTA reduction.
    __syncthreads();
    red[tid] = llacc;
    __syncthreads();
    for (int off = 256; off > 0; off >>= 1) {
        if (tid < off) red[tid] += red[tid + off];
        __syncthreads();
    }
    if (tid == 0) g_partLL[blockIdx.x] = red[0];
}

// ---------------------------------------------------------------------------
// Kernel 4: final deterministic loglik sum (double accumulation).
// ---------------------------------------------------------------------------
__global__ __launch_bounds__(256) void final_kernel(float* __restrict__ out) {
    __shared__ double red[256];
    int tid = threadIdx.x;
    double s = 0.0;
    for (int i = tid; i < 1024; i += 256) s += (double)g_partLL[i];
    red[tid] = s;
    __syncthreads();
    for (int off = 128; off > 0; off >>= 1) {
        if (tid < off) red[tid] += red[tid + off];
        __syncthreads();
    }
    if (tid == 0) out[0] = (float)red[0];
}

// ---------------------------------------------------------------------------
extern "C" void kernel_launch(void* const* d_in, const int* in_sizes, int n_in,
                              void* d_out, int out_size) {
    const float* obs   = (const float*)d_in[0];   // [K, N]
    const float* Beta  = (const float*)d_in[1];   // [K]
    const float* Alpha = (const float*)d_in[2];   // [K, K]
    float* out = (float*)d_out;                   // [1 + K*N + K*N]

    scan_kernel<<<NCHUNK, 256>>>(obs, Beta);
    prep_kernel<<<1, 256>>>();

    cudaFuncSetAttribute(gemm_kernel, cudaFuncAttributeMaxDynamicSharedMemorySize, SMEM_BYTES);
    gemm_kernel<<<GRID, 512, SMEM_BYTES>>>(obs, Alpha, out);

    final_kernel<<<1, 256>>>(out);
}

// round 12
// speedup vs baseline: 2.3282x; 1.0102x over previous
#include <cuda_runtime.h>
#include <cuda_bf16.h>
#include <cstdint>

// Problem constants (K=256, N=65536 fixed)
#define KDIM    256
#define NTIME   65536
#define NCHUNK  512
#define CHUNKL  128
#define WARMUP  32

#define NTILES  1024          // 1024 tiles x 64 output columns t = 0..65535
#define GRID    148           // single wave, persistent tiles

#define CS      36            // u32 (bf16-pair) per k-chunk in permuted smem
#define RS      144           // u32 per row (4 chunks x 36); 576B, 16B-multiple
#define EPI_STRIDE 68         // floats per row of epilogue staging (mult of 4)

// Scratch (device globals; zero-initialized at module load)
__device__ __align__(16) __nv_bfloat16 g_S[(size_t)NTIME * KDIM]; // S[t][k]; row t=0 stays 0
__device__ float g_Mu0[KDIM];
__device__ float g_rowpart[NCHUNK * KDIM];
__device__ float g_partLL[GRID];
__device__ unsigned g_scanCnt;
__device__ unsigned g_gemmCnt;

__device__ __forceinline__ uint32_t pack_bf16(float lo, float hi) {
    __nv_bfloat162 p = __floats2bfloat162_rn(lo, hi);
    return *reinterpret_cast<uint32_t*>(&p);
}

// ---------------------------------------------------------------------------
// Kernel 1: chunked exponential scan (WARMUP makes chunks independent; decay
// <= e^-1 so carry error <= e^-32). Stores bf16 S at t = j+1, coalesced in k.
// Last-arriving block computes Mu0 (deterministic fixed-order sum).
// ---------------------------------------------------------------------------
__global__ __launch_bounds__(256) void scan_kernel(const float* __restrict__ obs,
                                                   const float* __restrict__ Beta) {
    int k = threadIdx.x;
    int c = blockIdx.x;
    float beta  = Beta[k];
    float decay = expf(-beta);

    const float* orow = obs + ((size_t)k << 16);
    int j0 = c << 7;

    float h = 0.f;
    if (c > 0) {
        const float4* wp = (const float4*)(orow + j0 - WARMUP);
        #pragma unroll
        for (int i = 0; i < WARMUP / 4; ++i) {
            float4 v = wp[i];
            h = decay * (h + v.x); h = decay * (h + v.y);
            h = decay * (h + v.z); h = decay * (h + v.w);
        }
    }

    float s = 0.f;
    const float4* mp = (const float4*)(orow + j0);
    __nv_bfloat16* srow = g_S + (((size_t)(j0 + 1)) << 8) + k;
    int nstore = 65535 - j0; if (nstore > CHUNKL) nstore = CHUNKL;

    #pragma unroll 4
    for (int q = 0; q < CHUNKL / 4; ++q) {
        float4 v = mp[q];
        float vv[4] = {v.x, v.y, v.z, v.w};
        #pragma unroll
        for (int e = 0; e < 4; ++e) {
            float o = vv[e];
            s += o;
            h = decay * (h + o);
            int i = (q << 2) + e;
            if (i < nstore) srow[(size_t)i << 8] = __float2bfloat16_rn(beta * h);
        }
    }
    g_rowpart[(c << 8) + k] = s;

    // last-arriving block computes Mu0
    __threadfence();
    __shared__ unsigned lastFlag;
    if (k == 0) lastFlag = atomicAdd(&g_scanCnt, 1);
    __syncthreads();
    if (lastFlag == NCHUNK - 1) {
        float t = 0.f;
        for (int cc = 0; cc < NCHUNK; ++cc) t += g_rowpart[(cc << 8) + k];
        g_Mu0[k] = t * (1.0f / (float)NTIME) / 10.0f + 0.01f;
        if (k == 0) g_scanCnt = 0;
    }
}

// ---------------------------------------------------------------------------
// Kernel 2: fused bf16 MMA GEMM (Lam = Alpha @ S^T per column) + softplus +
// lams0/lams1 stores + loglik. One CTA per SM, full M=256, N=64 per tile,
// K=256. A held in smem bf16 (pair-permuted) for the whole kernel.
// Last CTA performs the final deterministic double-precision loglik sum.
// ---------------------------------------------------------------------------
__device__ __forceinline__ void mma_bf16(float* d, uint32_t a0, uint32_t a1,
                                         uint32_t a2, uint32_t a3,
                                         uint32_t b0, uint32_t b1) {
    asm volatile(
        "mma.sync.aligned.m16n8k16.row.col.f32.bf16.bf16.f32 "
        "{%0,%1,%2,%3}, {%4,%5,%6,%7}, {%8,%9}, {%0,%1,%2,%3};"
        : "+f"(d[0]), "+f"(d[1]), "+f"(d[2]), "+f"(d[3])
        : "r"(a0), "r"(a1), "r"(a2), "r"(a3), "r"(b0), "r"(b1));
}

#define SMEM_U32   (256 * RS + 64 * RS)
#define SMEM_BYTES ((SMEM_U32 + 256 + 512) * 4)

__global__ __launch_bounds__(512, 1) void gemm_kernel(const float* __restrict__ obs,
                                                      const float* __restrict__ Alpha,
                                                      float* __restrict__ out) {
    extern __shared__ uint32_t smu[];
    uint32_t* As  = smu;                        // [256][RS] bf16-pairs, permuted
    uint32_t* Ss  = smu + 256 * RS;             // [64][RS]; overlaid as epi[128][EPI_STRIDE] floats
    float*    epi = (float*)Ss;
    float*   Mu0s = (float*)(smu + SMEM_U32);
    float*    red = Mu0s + 256;

    int tid   = threadIdx.x;
    int tile0 = blockIdx.x;

    // ---- Stage full Alpha into smem (bf16 pairs, permuted), once.
    {
        int r = tid >> 1, half = tid & 1;
        const float4* src = (const float4*)(Alpha + ((size_t)r << 8)) + half * 32;
        uint32_t* dst = As + r * RS;
        #pragma unroll
        for (int i = 0; i < 32; ++i) {
            int f = half * 32 + i;              // float4 index: k = 4f..4f+3, pairs 2f, 2f+1
            float4 v = src[i];
            int j0 = 2 * f, j1 = 2 * f + 1;
            dst[(j0 & 3) * CS + (j0 >> 2)] = pack_bf16(v.x, v.y);
            dst[(j1 & 3) * CS + (j1 >> 2)] = pack_bf16(v.z, v.w);
        }
    }
    if (tid < 256) Mu0s[tid] = g_Mu0[tid];

    int warp = tid >> 5, lane = tid & 31;
    int wm = warp & 3, wn = warp >> 2;          // 4x4 warp grid: M=64, N=16 per warp
    int g  = lane >> 2, t = lane & 3;
    const uint32_t* aB = As + (wm * 64 + g) * RS + t * CS;
    const uint32_t* bB = Ss + (wn * 16 + g) * RS + t * CS;

    // ---- S tile register prefetch: 64 rows x 128 u32; 8 threads/row, 4 uint4 each.
    int scol = tid >> 3, sq = tid & 7;
    uint4 v[4];
    {
        const uint4* src = (const uint4*)g_S + ((size_t)(tile0 * 64 + scol) * 32) + sq * 4;
        #pragma unroll
        for (int i = 0; i < 4; ++i) v[i] = src[i];
    }

    int erow = tid >> 2;                        // epilogue row 0..127 within half
    int seg  = (tid & 3) << 4;                  // 16-col contiguous span

    float llacc = 0.f;

    for (int tile = tile0; tile < NTILES; tile += GRID) {
        __syncthreads();                        // prev epi reads done; As staged (first iter)
        // STS prefetched S tile (permuted): u32 j -> pos (j&3)*CS + (j>>2)
        {
            uint32_t* dst = Ss + scol * RS;
            #pragma unroll
            for (int i = 0; i < 4; ++i) {
                int u = 4 * sq + i;             // j = 4u .. covers chunks 0..3 at index u
                dst[u]          = v[i].x;
                dst[CS + u]     = v[i].y;
                dst[2 * CS + u] = v[i].z;
                dst[3 * CS + u] = v[i].w;
            }
        }
        __syncthreads();
        int ntile = tile + GRID;
        if (ntile < NTILES) {                   // overlap next LDG with MMA
            const uint4* src = (const uint4*)g_S + ((size_t)(ntile * 64 + scol) * 32) + sq * 4;
            #pragma unroll
            for (int i = 0; i < 4; ++i) v[i] = src[i];
        }

        float acc[4][2][4];
        #pragma unroll
        for (int mt = 0; mt < 4; ++mt)
            #pragma unroll
            for (int nt = 0; nt < 2; ++nt)
                #pragma unroll
                for (int q = 0; q < 4; ++q) acc[mt][nt][q] = 0.f;

        #pragma unroll
        for (int q = 0; q < 8; ++q) {           // each q = 2 k16 blocks
            uint4 Ag[4], Ah[4], Bn[2];
            #pragma unroll
            for (int mt = 0; mt < 4; ++mt) {
                Ag[mt] = *(const uint4*)(aB + (mt * 16) * RS + 4 * q);
                Ah[mt] = *(const uint4*)(aB + (mt * 16 + 8) * RS + 4 * q);
            }
            #pragma unroll
            for (int nt = 0; nt < 2; ++nt)
                Bn[nt] = *(const uint4*)(bB + (nt * 8) * RS + 4 * q);
            #pragma unroll
            for (int mt = 0; mt < 4; ++mt)
                #pragma unroll
                for (int nt = 0; nt < 2; ++nt) {
                    mma_bf16(acc[mt][nt], Ag[mt].x, Ah[mt].x, Ag[mt].y, Ah[mt].y,
                             Bn[nt].x, Bn[nt].y);
                    mma_bf16(acc[mt][nt], Ag[mt].z, Ah[mt].z, Ag[mt].w, Ah[mt].w,
                             Bn[nt].z, Bn[nt].w);
                }
        }

        // ---- Two half-passes: stage acc rows into epi buffer, stream epilogue.
        #pragma unroll
        for (int hp = 0; hp < 2; ++hp) {
            __syncthreads();                    // MMA Ss reads / prev epi reads done
            if ((wm >> 1) == hp) {
                int lr = (wm & 1) * 64 + g;     // local row (plus mt*16, +8)
                #pragma unroll
                for (int mt = 0; mt < 4; ++mt)
                    #pragma unroll
                    for (int nt = 0; nt < 2; ++nt) {
                        int col = wn * 16 + nt * 8 + 2 * t;
                        float* e0 = epi + (lr + mt * 16) * EPI_STRIDE + col;
                        *(float2*)e0 = make_float2(acc[mt][nt][0], acc[mt][nt][1]);
                        *(float2*)(e0 + 8 * EPI_STRIDE) =
                            make_float2(acc[mt][nt][2], acc[mt][nt][3]);
                    }
            }
            __syncthreads();

            // Coalesced streaming epilogue: 16 contiguous columns per thread.
            int row = hp * 128 + erow;
            float mu = Mu0s[row];
            size_t grow = ((size_t)row) << 16;
            int t0 = (tile << 6) + seg;
            const float* esrc = epi + erow * EPI_STRIDE + seg;

            float lam[16];
            #pragma unroll
            for (int i = 0; i < 4; ++i) {
                float4 xv = *(const float4*)(esrc + (i << 2));
                float xs[4] = {xv.x, xv.y, xv.z, xv.w};
                #pragma unroll
                for (int e = 0; e < 4; ++e) {
                    float x = xs[e];                      // x >= 0
                    lam[(i << 2) + e] = x + __logf(1.0f + __expf(-x));
                }
            }
            if (tile == 0 && seg == 0) lam[0] = 0.f;      // column t=0: lams1 = 0

            const float4* op = (const float4*)(obs + grow + t0);
            #pragma unroll
            for (int i = 0; i < 4; ++i) {
                float4 ov = op[i];
                llacc += ov.x * __logf(mu + lam[(i << 2) + 0] + 1e-5f) - lam[(i << 2) + 0];
                llacc += ov.y * __logf(mu + lam[(i << 2) + 1] + 1e-5f) - lam[(i << 2) + 1];
                llacc += ov.z * __logf(mu + lam[(i << 2) + 2] + 1e-5f) - lam[(i << 2) + 2];
                llacc += ov.w * __logf(mu + lam[(i << 2) + 3] + 1e-5f) - lam[(i << 2) + 3];
            }
            llacc -= 16.f * mu;

            float* p0 = out + 1 + grow + t0;                           // lams0
            float* p1 = out + 1 + (((size_t)KDIM) << 16) + grow + t0;  // lams1
            // p0/p1 are (16B-4) aligned: 3 scalars, 3x float4, 1 scalar.
            p1[0] = lam[0]; p1[1] = lam[1]; p1[2] = lam[2];
            *(float4*)(p1 + 3)  = make_float4(lam[3],  lam[4],  lam[5],  lam[6]);
            *(float4*)(p1 + 7)  = make_float4(lam[7],  lam[8],  lam[9],  lam[10]);
            *(float4*)(p1 + 11) = make_float4(lam[11], lam[12], lam[13], lam[14]);
            p1[15] = lam[15];
            float4 muv = make_float4(mu, mu, mu, mu);
            p0[0] = mu; p0[1] = mu; p0[2] = mu;
            *(float4*)(p0 + 3) = muv; *(float4*)(p0 + 7) = muv; *(float4*)(p0 + 11) = muv;
            p0[15] = mu;
        }
    }

    // ---- Deterministic CTA reduction of loglik partial.
    __syncthreads();
    red[tid] = llacc;
    __syncthreads();
    for (int off = 256; off > 0; off >>= 1) {
        if (tid < off) red[tid] += red[tid + off];
        __syncthreads();
    }
    if (tid == 0) {
        g_partLL[blockIdx.x] = red[0];
        __threadfence();
    }
    __syncthreads();

    // ---- Last CTA: final deterministic double-precision sum (reuses epi).
    __shared__ unsigned lastFlag;
    if (tid == 0) lastFlag = atomicAdd(&g_gemmCnt, 1);
    __syncthreads();
    if (lastFlag == GRID - 1) {
        double* dred = (double*)epi;
        if (tid < 256) dred[tid] = (tid < GRID) ? (double)g_partLL[tid] : 0.0;
        __syncthreads();
        for (int off = 128; off > 0; off >>= 1) {
            if (tid < off) dred[tid] += dred[tid + off];
            __syncthreads();
        }
        if (tid == 0) { out[0] = (float)dred[0]; g_gemmCnt = 0; }
    }
}

// ---------------------------------------------------------------------------
extern "C" void kernel_launch(void* const* d_in, const int* in_sizes, int n_in,
                              void* d_out, int out_size) {
    const float* obs   = (const float*)d_in[0];   // [K, N]
    const float* Beta  = (const float*)d_in[1];   // [K]
    const float* Alpha = (const float*)d_in[2];   // [K, K]
    float* out = (float*)d_out;                   // [1 + K*N + K*N]

    scan_kernel<<<NCHUNK, 256>>>(obs, Beta);

    cudaFuncSetAttribute(gemm_kernel, cudaFuncAttributeMaxDynamicSharedMemorySize, SMEM_BYTES);
    gemm_kernel<<<GRID, 512, SMEM_BYTES>>>(obs, Alpha, out);
}